// round 12
// baseline (speedup 1.0000x reference)
#include <cuda_runtime.h>

#define LOG2E 1.4426950408889634f
typedef unsigned long long u64;

// ---------------- f32x2 packed-math helpers (Blackwell dual-FP32) ----------
__device__ __forceinline__ u64 splat2(float x){
  u64 r; asm("mov.b64 %0, {%1,%1};" : "=l"(r) : "f"(x)); return r;
}
__device__ __forceinline__ u64 pack2(float a, float b){
  u64 r; asm("mov.b64 %0, {%1,%2};" : "=l"(r) : "f"(a), "f"(b)); return r;
}
__device__ __forceinline__ void unpack2(u64 v, float& a, float& b){
  asm("mov.b64 {%0,%1}, %2;" : "=f"(a), "=f"(b) : "l"(v));
}
__device__ __forceinline__ u64 ffma2(u64 a, u64 b, u64 c){
  u64 d; asm("fma.rn.f32x2 %0, %1, %2, %3;" : "=l"(d) : "l"(a), "l"(b), "l"(c));
  return d;
}
__device__ __forceinline__ u64 fmul2(u64 a, u64 b){
  u64 d; asm("mul.rn.f32x2 %0, %1, %2;" : "=l"(d) : "l"(a), "l"(b)); return d;
}
__device__ __forceinline__ float fexp2(float x){
  float y; asm("ex2.approx.ftz.f32 %0, %1;" : "=f"(y) : "f"(x)); return y;
}

// ---------------- scratch (device globals; no allocation allowed) ----------
__device__ float g_Q [8192*128];
__device__ float g_K [8192*128];
__device__ float g_V [8192*128];
__device__ float g_O [8192*128];
__device__ float g_Y [8192*128];
__device__ float g_FF[8192*512];
__device__ float g_red[2][8][2];   // [stage][sample][sum, sumsq]

// ---------------- GEMM microkernel: C[64][128], K-chunk=128, 256 thr -------
// tr = tid>>5 owns rows tr*8..+7; lane owns cols lane*4..+3 (2 f32x2 pairs).
__device__ __forceinline__ void gemm_compute2(const float* As, const float* Ws,
                                              u64 acc[8][2], int r0, int lane){
  #pragma unroll
  for (int k4 = 0; k4 < 32; k4++){
    u64 b[4][2];
    #pragma unroll
    for (int j = 0; j < 4; j++){
      ulonglong2 bv = ((const ulonglong2*)Ws)[(k4*4+j)*32 + lane];
      b[j][0] = bv.x; b[j][1] = bv.y;
    }
    #pragma unroll
    for (int i = 0; i < 8; i++){
      float4 a = ((const float4*)As)[(r0+i)*32 + k4];
      u64 s0 = splat2(a.x), s1 = splat2(a.y), s2 = splat2(a.z), s3 = splat2(a.w);
      acc[i][0] = ffma2(s0, b[0][0], acc[i][0]);
      acc[i][1] = ffma2(s0, b[0][1], acc[i][1]);
      acc[i][0] = ffma2(s1, b[1][0], acc[i][0]);
      acc[i][1] = ffma2(s1, b[1][1], acc[i][1]);
      acc[i][0] = ffma2(s2, b[2][0], acc[i][0]);
      acc[i][1] = ffma2(s2, b[2][1], acc[i][1]);
      acc[i][0] = ffma2(s3, b[3][0], acc[i][0]);
      acc[i][1] = ffma2(s3, b[3][1], acc[i][1]);
    }
  }
}

__device__ __forceinline__ void ln_reduce_store(float s, float sq, float* sm,
                                                int tid, int b, int which){
  #pragma unroll
  for (int off = 16; off; off >>= 1){
    s  += __shfl_xor_sync(0xffffffffu, s,  off);
    sq += __shfl_xor_sync(0xffffffffu, sq, off);
  }
  __syncthreads();
  if ((tid & 31) == 0){ sm[tid>>5] = s; sm[8 + (tid>>5)] = sq; }
  __syncthreads();
  if (tid == 0){
    float S = 0.f, SQ = 0.f;
    int nw = blockDim.x >> 5;
    for (int w = 0; w < nw; w++){ S += sm[w]; SQ += sm[8+w]; }
    atomicAdd(&g_red[which][b][0], S);
    atomicAdd(&g_red[which][b][1], SQ);
  }
}

__device__ __forceinline__ void ln_params(int which, int b, float& mean, float& rstd){
  float s  = g_red[which][b][0];
  float sq = g_red[which][b][1];
  const float M = 131072.f;
  mean = s / M;
  float var = (sq - s*s/M) / (M - 1.f);
  rstd = rsqrtf(var + 1e-5f);
}

// ---------------- K1: QKV projections (+ zero g_red from block (0,0)) ------
__global__ void __launch_bounds__(256) qkv_kernel(const float* __restrict__ x,
    const float* __restrict__ Wq, const float* __restrict__ Wk,
    const float* __restrict__ Wv){
  extern __shared__ float sm[];
  float* As = sm;             // 64*128
  float* Ws = sm + 64*128;    // 128*128
  int row0 = blockIdx.x * 64;
  const float* W = (blockIdx.y==0) ? Wq : (blockIdx.y==1 ? Wk : Wv);
  float* outp    = (blockIdx.y==0) ? g_Q : (blockIdx.y==1 ? g_K : g_V);
  int tid = threadIdx.x;

  if (blockIdx.x == 0 && blockIdx.y == 0 && tid < 32)
    ((float*)g_red)[tid] = 0.f;

  #pragma unroll
  for (int rep = 0; rep < 8; rep++){
    int idx = rep*256 + tid;
    ((float4*)As)[idx] = ((const float4*)(x + (size_t)row0*128))[idx];
  }
  #pragma unroll
  for (int rep = 0; rep < 16; rep++){
    int idx = rep*256 + tid;               // Ws[e][j], j = h*32+k
    int e = idx >> 5, j4 = idx & 31;
    ((float4*)Ws)[idx] =
      *(const float4*)(W + ((j4>>3)<<12) + (e<<5) + ((j4&7)<<2));
  }
  __syncthreads();

  int tr = tid >> 5, lane = tid & 31;
  int r0 = tr*8, c0 = lane*4;
  u64 acc[8][2];
  #pragma unroll
  for (int i=0;i<8;i++){ acc[i][0]=splat2(0.f); acc[i][1]=splat2(0.f); }
  gemm_compute2(As, Ws, acc, r0, lane);
  #pragma unroll
  for (int i=0;i<8;i++){
    float c[4];
    unpack2(acc[i][0], c[0], c[1]); unpack2(acc[i][1], c[2], c[3]);
    *(float4*)(outp + (size_t)(row0+r0+i)*128 + c0) =
      make_float4(c[0],c[1],c[2],c[3]);
  }
}

// ---------------- K2: fused attention, 512 threads -------------------------
// grid (16, 8): blockIdx.x = 64-query tile, blockIdx.y = batch.
// Smat rows (4 heads * 64 q-rows), stride 68 floats, with column swizzle:
//   phys_col4 = (mi>>2) ^ ((row>>3)&7)   (XOR within the 16 float4 slots)
// -> score float4 stores spread over 8 bank-groups (was same-bank 8-way).
// Softmax is row-permutation-invariant; PV recovers logical columns in ALU.
#define SM_ST 68
__global__ void __launch_bounds__(512,1) attn_kernel(
    const float* __restrict__ in2, float* __restrict__ out2,
    const float* __restrict__ Ws1, const float* __restrict__ bs1,
    const float* __restrict__ Ws2, const float* __restrict__ bs2){
  extern __shared__ float sm[];
  float* Qs      = sm;               // 64*128 XOR-swizzled (16B granule)
  float* Ks      = Qs + 8192;        // 64*128 XOR-swizzled
  float* Vs      = Ks + 8192;        // 64*128 plain
  float* Smat    = Vs + 8192;        // 4*64*SM_ST (swizzled cols)
  float* alpha_s = Smat + 4*64*SM_ST;// 256
  float* rsum_s  = alpha_s + 256;    // 256
  float* mw      = rsum_s + 256;     // 112 (8B-aligned)

  int tid = threadIdx.x;
  int n0  = blockIdx.x * 64;
  int b   = blockIdx.y;

  if (tid < 64)       mw[tid] = Ws1[tid];
  else if (tid < 72)  mw[tid] = bs1[tid-64];
  else if (tid < 104) mw[tid] = Ws2[tid-72];
  else if (tid < 108) mw[tid] = bs2[tid-104];

  // MLP layer-1 weights in registers, packed over the 8 output channels
  u64 w1[8][4], b1[4];
  #pragma unroll
  for (int i=0;i<8;i++)
    #pragma unroll
    for (int jp=0;jp<4;jp++)
      w1[i][jp] = *(const u64*)(Ws1 + i*8 + 2*jp);
  #pragma unroll
  for (int jp=0;jp<4;jp++) b1[jp] = *(const u64*)(bs1 + 2*jp);

  // load Q tile (swizzled: k4 ^= (r>>3)&7)
  {
    const float* Qg = g_Q + ((size_t)(b*1024 + n0))*128;
    #pragma unroll
    for (int rep = 0; rep < 4; rep++){
      int idx = rep*512 + tid; int r = idx>>5, k4 = idx&31;
      float4 v = ((const float4*)Qg)[idx];
      *(float4*)(Qs + r*128 + ((k4 ^ ((r>>3)&7))<<2)) = v;
    }
  }

  int h = tid >> 7, t = tid & 127;
  int s_ni0 = (t&7)*8,  s_mi0 = (t>>3)*4;     // scores: 8 rows x 4 cols
  int s_pc4 = ((t>>3) ^ (t&7)) << 2;          // swizzled phys col offset
  int p_ni0 = (t>>3)*4, p_k0  = (t&7)*4;      // PV: 4 rows x 4 cols
  int p_x   = (t>>4) & 7;                     // PV row-group xor term
  int sm_row = tid >> 1, sm_half = tid & 1;   // softmax: half-row / thread
  int m_ni = tid >> 3, m_mi0 = (tid&7)*8;     // MLP: 8 elems per thread
  int m_x  = (m_ni >> 3) & 7;                 // MLP row-group xor term

  u64 O2[4][2];
  #pragma unroll
  for (int i=0;i<4;i++){ O2[i][0]=splat2(0.f); O2[i][1]=splat2(0.f); }
  float rmax = -1e30f, rsum = 0.f;
  const u64 log2e2 = splat2(LOG2E);

  const float* in2b = in2  + (size_t)b*1048576;
  float*       o2b  = out2 + (size_t)b*1048576;

  for (int it = 0; it < 16; it++){
    int m0 = it*64;
    __syncthreads();   // prev PV / Smat reads done
    {
      const float* Kg = g_K + ((size_t)(b*1024 + m0))*128;
      const float* Vg = g_V + ((size_t)(b*1024 + m0))*128;
      #pragma unroll
      for (int rep = 0; rep < 4; rep++){
        int idx = rep*512 + tid; int r = idx>>5, k4 = idx&31;
        float4 kv = ((const float4*)Kg)[idx];
        *(float4*)(Ks + r*128 + ((k4 ^ ((r>>3)&7))<<2)) = kv;
        float4 vv = ((const float4*)Vg)[idx];
        *(float4*)(Vs + r*128 + (k4<<2)) = vv;
      }
    }
    __syncthreads();

    // ---- scores: 8x4 tile / thread, float4 operand loads -----------------
    {
      u64 acc2[8][2];
      #pragma unroll
      for (int i=0;i<8;i++){ acc2[i][0]=splat2(0.f); acc2[i][1]=splat2(0.f); }
      #pragma unroll
      for (int kk4 = 0; kk4 < 8; kk4++){
        int kidx = (h<<3) + kk4;
        float4 a4[8], b4[4];
        #pragma unroll
        for (int i=0;i<8;i++){
          int r = s_ni0 + i;
          a4[i] = *(const float4*)(Qs + r*128 + ((kidx ^ (r>>3))<<2));
        }
        #pragma unroll
        for (int j=0;j<4;j++){
          int r = s_mi0 + j;
          b4[j] = *(const float4*)(Ks + r*128 + ((kidx ^ (r>>3))<<2));
        }
        #pragma unroll
        for (int kk=0; kk<4; kk++){
          u64 bp0 = pack2(((const float*)&b4[0])[kk], ((const float*)&b4[1])[kk]);
          u64 bp1 = pack2(((const float*)&b4[2])[kk], ((const float*)&b4[3])[kk]);
          #pragma unroll
          for (int i=0;i<8;i++){
            u64 sa = splat2(((const float*)&a4[i])[kk]);
            acc2[i][0] = ffma2(sa, bp0, acc2[i][0]);
            acc2[i][1] = ffma2(sa, bp1, acc2[i][1]);
          }
        }
      }
      #pragma unroll
      for (int i=0;i<8;i++){
        float c[4];
        unpack2(acc2[i][0], c[0], c[1]); unpack2(acc2[i][1], c[2], c[3]);
        *(float4*)(Smat + ((h<<6) + s_ni0 + i)*SM_ST + s_pc4) =
          make_float4(c[0],c[1],c[2],c[3]);
      }
    }
    __syncthreads();

    // ---- 8->8(relu)->4 MLP, fused input2 read + passthrough write --------
    {
      const float* p0 = in2b + ((size_t)(n0+m_ni)<<10) + m0 + m_mi0;
      float*       q0 = o2b  + ((size_t)(n0+m_ni)<<10) + m0 + m_mi0;
      float4 ta[4], tb[4];
      #pragma unroll
      for (int hh=0; hh<4; hh++){
        ta[hh] = *(const float4*)(p0 + (size_t)hh*8388608);
        tb[hh] = *(const float4*)(p0 + (size_t)hh*8388608 + 4);
        *(float4*)(q0 + (size_t)hh*8388608)     = ta[hh];
        *(float4*)(q0 + (size_t)hh*8388608 + 4) = tb[hh];
      }
      #pragma unroll
      for (int e=0; e<8; e++){
        int mi = m_mi0 + e;
        int off = ((((mi>>2) ^ m_x))<<2) + (mi&3);   // swizzled word in row
        float x[8];
        #pragma unroll
        for (int hh=0; hh<4; hh++)
          x[hh] = Smat[((hh<<6)+m_ni)*SM_ST + off];
        #pragma unroll
        for (int hh=0; hh<4; hh++)
          x[4+hh] = (e<4) ? ((const float*)&ta[hh])[e]
                          : ((const float*)&tb[hh])[e-4];
        u64 z2[4] = { b1[0], b1[1], b1[2], b1[3] };
        #pragma unroll
        for (int i=0;i<8;i++){
          u64 sx = splat2(x[i]);
          #pragma unroll
          for (int jp=0;jp<4;jp++) z2[jp] = ffma2(sx, w1[i][jp], z2[jp]);
        }
        u64 y2[2];
        y2[0] = *(const u64*)(mw+104);
        y2[1] = *(const u64*)(mw+106);
        #pragma unroll
        for (int jp=0;jp<4;jp++){
          float zl, zh; unpack2(z2[jp], zl, zh);
          zl = fmaxf(zl, 0.f); zh = fmaxf(zh, 0.f);
          u64 sl = splat2(zl), sh = splat2(zh);
          int j0 = 2*jp, j1 = 2*jp+1;
          y2[0] = ffma2(sl, *(const u64*)(mw + 72 + j0*4),     y2[0]);
          y2[1] = ffma2(sl, *(const u64*)(mw + 72 + j0*4 + 2), y2[1]);
          y2[0] = ffma2(sh, *(const u64*)(mw + 72 + j1*4),     y2[0]);
          y2[1] = ffma2(sh, *(const u64*)(mw + 72 + j1*4 + 2), y2[1]);
        }
        y2[0] = fmul2(y2[0], log2e2);
        y2[1] = fmul2(y2[1], log2e2);
        float y[4];
        unpack2(y2[0], y[0], y[1]); unpack2(y2[1], y[2], y[3]);
        #pragma unroll
        for (int hh=0;hh<4;hh++)
          Smat[((hh<<6)+m_ni)*SM_ST + off] = y[hh];
      }
    }
    __syncthreads();

    // ---- online softmax: thread pair per row (physical halves) -----------
    {
      float* Sr = Smat + sm_row*SM_ST + sm_half*32;
      float mt = -1e30f;
      #pragma unroll
      for (int q=0; q<16; q++){
        float2 v = *(const float2*)(Sr + 2*q);
        mt = fmaxf(mt, fmaxf(v.x, v.y));
      }
      float mo = __shfl_xor_sync(0xffffffffu, mt, 1);
      float mnew = fmaxf(rmax, fmaxf(mt, mo));
      float al = fexp2(rmax - mnew);
      float st = 0.f;
      #pragma unroll
      for (int q=0; q<16; q++){
        float2 v = *(const float2*)(Sr + 2*q);
        float p0 = fexp2(v.x - mnew);
        float p1 = fexp2(v.y - mnew);
        *(float2*)(Sr + 2*q) = make_float2(p0, p1);
        st += p0 + p1;
      }
      st += __shfl_xor_sync(0xffffffffu, st, 1);
      rsum = rsum*al + st;
      rmax = mnew;
      if (!sm_half){ alpha_s[sm_row] = al; rsum_s[sm_row] = rsum; }
    }
    __syncthreads();

    // ---- rescale + P @ V (4x4 tile; P linear u64, V via de-swizzle) ------
    {
      #pragma unroll
      for (int i=0;i<4;i++){
        u64 al = splat2(alpha_s[(h<<6) + p_ni0 + i]);
        O2[i][0] = fmul2(O2[i][0], al);
        O2[i][1] = fmul2(O2[i][1], al);
      }
      const float* pbase = Smat + ((h<<6)+p_ni0)*SM_ST;
      const float* vbase = Vs + (h<<5) + p_k0;
      #pragma unroll 8
      for (int mi2 = 0; mi2 < 32; mi2++){
        int pb = mi2 >> 1;
        int c0 = (((pb ^ p_x))<<2) + ((mi2&1)<<1);   // logical col of pp.x
        ulonglong2 vv0 = *(const ulonglong2*)(vbase + c0*128);
        ulonglong2 vv1 = *(const ulonglong2*)(vbase + (c0+1)*128);
        #pragma unroll
        for (int i=0;i<4;i++){
          float2 pp = *(const float2*)(pbase + i*SM_ST + 2*mi2);
          u64 s0 = splat2(pp.x), s1 = splat2(pp.y);
          O2[i][0] = ffma2(s0, vv0.x, O2[i][0]);
          O2[i][1] = ffma2(s0, vv0.y, O2[i][1]);
          O2[i][0] = ffma2(s1, vv1.x, O2[i][0]);
          O2[i][1] = ffma2(s1, vv1.y, O2[i][1]);
        }
      }
    }
  }

  // final normalize + write heads output
  float* Og = g_O + ((size_t)(b*1024 + n0))*128;
  #pragma unroll
  for (int i=0;i<4;i++){
    float inv = 1.f / rsum_s[(h<<6) + p_ni0 + i];
    float c[4];
    unpack2(O2[i][0], c[0], c[1]); unpack2(O2[i][1], c[2], c[3]);
    *(float4*)(Og + (size_t)(p_ni0+i)*128 + (h<<5) + p_k0) =
      make_float4(c[0]*inv, c[1]*inv, c[2]*inv, c[3]*inv);
  }
}

// ---------------- K3: out-projection + residual + LN0 sums -----------------
__global__ void __launch_bounds__(256) outproj_kernel(
    const float* __restrict__ input1, const float* __restrict__ Wout){
  extern __shared__ float sm[];
  float* As = sm; float* Ws = sm + 64*128;
  int row0 = blockIdx.x * 64; int tid = threadIdx.x;
  #pragma unroll
  for (int rep=0; rep<8; rep++){
    int idx = rep*256 + tid;
    ((float4*)As)[idx] = ((const float4*)(g_O + (size_t)row0*128))[idx];
  }
  #pragma unroll
  for (int rep=0; rep<16; rep++){
    int idx = rep*256 + tid;
    ((float4*)Ws)[idx] = ((const float4*)Wout)[idx];
  }
  __syncthreads();
  int tr = tid>>5, lane = tid&31, r0 = tr*8, c0 = lane*4;
  u64 acc[8][2];
  #pragma unroll
  for (int i=0;i<8;i++){ acc[i][0]=splat2(0.f); acc[i][1]=splat2(0.f); }
  gemm_compute2(As, Ws, acc, r0, lane);
  float s=0.f, sq=0.f;
  #pragma unroll
  for (int i=0;i<8;i++){
    float c[4];
    unpack2(acc[i][0], c[0], c[1]); unpack2(acc[i][1], c[2], c[3]);
    float4 res = *(const float4*)(input1 + (size_t)(row0+r0+i)*128 + c0);
    float4 o = make_float4(c[0]+res.x, c[1]+res.y, c[2]+res.z, c[3]+res.w);
    *(float4*)(g_Y + (size_t)(row0+r0+i)*128 + c0) = o;
    s  += o.x+o.y+o.z+o.w;
    sq += o.x*o.x+o.y*o.y+o.z*o.z+o.w*o.w;
  }
  ln_reduce_store(s, sq, sm, tid, row0>>10, 0);
}

// ---------------- K4: FF1 (inline LN0 of g_Y, relu) ------------------------
__global__ void __launch_bounds__(256) ff1_kernel(const float* __restrict__ Wff1){
  extern __shared__ float sm[];
  float* As = sm; float* Ws = sm + 64*128;
  int row0 = blockIdx.x * 64, ct = blockIdx.y, tid = threadIdx.x;
  float mean, rstd; ln_params(0, row0>>10, mean, rstd);
  #pragma unroll
  for (int rep=0; rep<8; rep++){
    int idx = rep*256 + tid;
    float4 v = ((const float4*)(g_Y + (size_t)row0*128))[idx];
    v.x=(v.x-mean)*rstd; v.y=(v.y-mean)*rstd;
    v.z=(v.z-mean)*rstd; v.w=(v.w-mean)*rstd;
    ((float4*)As)[idx] = v;
  }
  #pragma unroll
  for (int rep=0; rep<16; rep++){
    int idx = rep*256 + tid;
    int e = idx>>5, c4 = idx&31;
    ((float4*)Ws)[idx] = *(const float4*)(Wff1 + (size_t)e*512 + ct*128 + c4*4);
  }
  __syncthreads();
  int tr = tid>>5, lane = tid&31, r0 = tr*8, c0 = lane*4;
  u64 acc[8][2];
  #pragma unroll
  for (int i=0;i<8;i++){ acc[i][0]=splat2(0.f); acc[i][1]=splat2(0.f); }
  gemm_compute2(As, Ws, acc, r0, lane);
  #pragma unroll
  for (int i=0;i<8;i++){
    float c[4];
    unpack2(acc[i][0], c[0], c[1]); unpack2(acc[i][1], c[2], c[3]);
    float4 o = make_float4(fmaxf(c[0],0.f), fmaxf(c[1],0.f),
                           fmaxf(c[2],0.f), fmaxf(c[3],0.f));
    *(float4*)(g_FF + (size_t)(row0+r0+i)*512 + ct*128 + c0) = o;
  }
}

// ---------------- K5: FF2 + residual (inline LN0) + LN1 sums ---------------
__global__ void __launch_bounds__(256) ff2_kernel(const float* __restrict__ Wff2){
  extern __shared__ float sm[];
  float* As = sm; float* Ws = sm + 64*128;
  int row0 = blockIdx.x * 64, tid = threadIdx.x;
  float mean, rstd; ln_params(0, row0>>10, mean, rstd);
  int tr = tid>>5, lane = tid&31, r0 = tr*8, c0 = lane*4;
  u64 acc[8][2];
  #pragma unroll
  for (int i=0;i<8;i++){ acc[i][0]=splat2(0.f); acc[i][1]=splat2(0.f); }
  for (int ch = 0; ch < 4; ch++){
    __syncthreads();
    #pragma unroll
    for (int rep=0; rep<8; rep++){
      int idx = rep*256 + tid; int r = idx>>5, k4 = idx&31;
      ((float4*)As)[idx] =
        *(const float4*)(g_FF + (size_t)(row0+r)*512 + ch*128 + k4*4);
    }
    #pragma unroll
    for (int rep=0; rep<16; rep++){
      int idx = rep*256 + tid;
      ((float4*)Ws)[idx] = ((const float4*)(Wff2 + (size_t)ch*16384))[idx];
    }
    __syncthreads();
    gemm_compute2(As, Ws, acc, r0, lane);
  }
  float s=0.f, sq=0.f;
  #pragma unroll
  for (int i=0;i<8;i++){
    float c[4];
    unpack2(acc[i][0], c[0], c[1]); unpack2(acc[i][1], c[2], c[3]);
    float4 res = *(const float4*)(g_Y + (size_t)(row0+r0+i)*128 + c0);
    res.x=(res.x-mean)*rstd; res.y=(res.y-mean)*rstd;
    res.z=(res.z-mean)*rstd; res.w=(res.w-mean)*rstd;
    float4 o = make_float4(c[0]+res.x, c[1]+res.y, c[2]+res.z, c[3]+res.w);
    *(float4*)(g_Y + (size_t)(row0+r0+i)*128 + c0) = o;   // own rows only
    s  += o.x+o.y+o.z+o.w;
    sq += o.x*o.x+o.y*o.y+o.z*o.z+o.w*o.w;
  }
  ln_reduce_store(s, sq, sm, tid, row0>>10, 1);
}

// ---------------- K6: final global LayerNorm (ddof=1) ----------------------
__global__ void __launch_bounds__(256) norm_kernel(float* __restrict__ extout){
  int id = blockIdx.x*256 + threadIdx.x;          // float4 index
  int b = (id*4) >> 17;
  float mean, rstd; ln_params(1, b, mean, rstd);
  float4 v = ((const float4*)g_Y)[id];
  v.x = (v.x-mean)*rstd; v.y = (v.y-mean)*rstd;
  v.z = (v.z-mean)*rstd; v.w = (v.w-mean)*rstd;
  ((float4*)extout)[id] = v;
}

// ---------------- launcher --------------------------------------------------
extern "C" void kernel_launch(void* const* d_in, const int* in_sizes, int n_in,
                              void* d_out, int out_size){
  const float* input1 = (const float*)d_in[0];
  const float* input2 = (const float*)d_in[1];
  const float* Wq  = (const float*)d_in[2];
  const float* Wk  = (const float*)d_in[3];
  const float* Wv  = (const float*)d_in[4];
  const float* Wo  = (const float*)d_in[5];
  const float* Ws1 = (const float*)d_in[6];
  const float* bs1 = (const float*)d_in[7];
  const float* Ws2 = (const float*)d_in[8];
  const float* bs2 = (const float*)d_in[9];
  const float* Wff1 = (const float*)d_in[10];
  const float* Wff2 = (const float*)d_in[11];
  float* out1 = (float*)d_out;
  float* out2 = out1 + 8*1024*128;      // input2 passthrough region

  const int GEMM_SMEM = (64*128 + 128*128)*4;                        // 98304
  const int ATTN_SMEM = (3*8192 + 4*64*SM_ST + 256 + 256 + 112)*4;   // 170432

  cudaFuncSetAttribute(qkv_kernel,     cudaFuncAttributeMaxDynamicSharedMemorySize, GEMM_SMEM);
  cudaFuncSetAttribute(attn_kernel,    cudaFuncAttributeMaxDynamicSharedMemorySize, ATTN_SMEM);
  cudaFuncSetAttribute(outproj_kernel, cudaFuncAttributeMaxDynamicSharedMemorySize, GEMM_SMEM);
  cudaFuncSetAttribute(ff1_kernel,     cudaFuncAttributeMaxDynamicSharedMemorySize, GEMM_SMEM);
  cudaFuncSetAttribute(ff2_kernel,     cudaFuncAttributeMaxDynamicSharedMemorySize, GEMM_SMEM);

  qkv_kernel<<<dim3(128,3), 256, GEMM_SMEM>>>(input1, Wq, Wk, Wv);
  attn_kernel<<<dim3(16,8), 512, ATTN_SMEM>>>(input2, out2, Ws1, bs1, Ws2, bs2);
  outproj_kernel<<<128, 256, GEMM_SMEM>>>(input1, Wo);
  ff1_kernel<<<dim3(128,4), 256, GEMM_SMEM>>>(Wff1);
  ff2_kernel<<<128, 256, GEMM_SMEM>>>(Wff2);
  norm_kernel<<<1024, 256>>>(out1);
}

// round 16
// speedup vs baseline: 1.3168x; 1.3168x over previous
#include <cuda_runtime.h>

#define LOG2E 1.4426950408889634f
typedef unsigned long long u64;
typedef unsigned int u32;

// ---------------- f32x2 packed-math helpers (Blackwell dual-FP32) ----------
__device__ __forceinline__ u64 splat2(float x){
  u64 r; asm("mov.b64 %0, {%1,%1};" : "=l"(r) : "f"(x)); return r;
}
__device__ __forceinline__ void unpack2(u64 v, float& a, float& b){
  asm("mov.b64 {%0,%1}, %2;" : "=f"(a), "=f"(b) : "l"(v));
}
__device__ __forceinline__ u64 ffma2(u64 a, u64 b, u64 c){
  u64 d; asm("fma.rn.f32x2 %0, %1, %2, %3;" : "=l"(d) : "l"(a), "l"(b), "l"(c));
  return d;
}
__device__ __forceinline__ u64 fmul2(u64 a, u64 b){
  u64 d; asm("mul.rn.f32x2 %0, %1, %2;" : "=l"(d) : "l"(a), "l"(b)); return d;
}
__device__ __forceinline__ float fexp2(float x){
  float y; asm("ex2.approx.ftz.f32 %0, %1;" : "=f"(y) : "f"(x)); return y;
}
// tf32 round-to-nearest (bits stay fp32-compatible)
__device__ __forceinline__ float tf32r(float x){
  u32 u; asm("cvt.rna.tf32.f32 %0, %1;" : "=r"(u) : "f"(x));
  return __uint_as_float(u);
}
// m16n8k8 tf32 MMA, D += A*B (fp32 accumulate in-place)
__device__ __forceinline__ void mma_tf32(float c[4], const u32 a[4], u32 b0, u32 b1){
  asm("mma.sync.aligned.m16n8k8.row.col.f32.tf32.tf32.f32 "
      "{%0,%1,%2,%3}, {%4,%5,%6,%7}, {%8,%9}, {%0,%1,%2,%3};"
      : "+f"(c[0]), "+f"(c[1]), "+f"(c[2]), "+f"(c[3])
      : "r"(a[0]), "r"(a[1]), "r"(a[2]), "r"(a[3]), "r"(b0), "r"(b1));
}

// ---------------- scratch (device globals; no allocation allowed) ----------
__device__ float g_Q [8192*128];
__device__ float g_K [8192*128];
__device__ float g_V [8192*128];
__device__ float g_O [8192*128];
__device__ float g_Y [8192*128];
__device__ float g_FF[8192*512];
__device__ float g_red[2][8][2];   // [stage][sample][sum, sumsq]

// ---------------- GEMM microkernel: C[64][128], K-chunk=128, 256 thr -------
__device__ __forceinline__ void gemm_compute2(const float* As, const float* Ws,
                                              u64 acc[8][2], int r0, int lane){
  #pragma unroll
  for (int k4 = 0; k4 < 32; k4++){
    u64 b[4][2];
    #pragma unroll
    for (int j = 0; j < 4; j++){
      ulonglong2 bv = ((const ulonglong2*)Ws)[(k4*4+j)*32 + lane];
      b[j][0] = bv.x; b[j][1] = bv.y;
    }
    #pragma unroll
    for (int i = 0; i < 8; i++){
      float4 a = ((const float4*)As)[(r0+i)*32 + k4];
      u64 s0 = splat2(a.x), s1 = splat2(a.y), s2 = splat2(a.z), s3 = splat2(a.w);
      acc[i][0] = ffma2(s0, b[0][0], acc[i][0]);
      acc[i][1] = ffma2(s0, b[0][1], acc[i][1]);
      acc[i][0] = ffma2(s1, b[1][0], acc[i][0]);
      acc[i][1] = ffma2(s1, b[1][1], acc[i][1]);
      acc[i][0] = ffma2(s2, b[2][0], acc[i][0]);
      acc[i][1] = ffma2(s2, b[2][1], acc[i][1]);
      acc[i][0] = ffma2(s3, b[3][0], acc[i][0]);
      acc[i][1] = ffma2(s3, b[3][1], acc[i][1]);
    }
  }
}

__device__ __forceinline__ void ln_reduce_store(float s, float sq, float* sm,
                                                int tid, int b, int which){
  #pragma unroll
  for (int off = 16; off; off >>= 1){
    s  += __shfl_xor_sync(0xffffffffu, s,  off);
    sq += __shfl_xor_sync(0xffffffffu, sq, off);
  }
  __syncthreads();
  if ((tid & 31) == 0){ sm[tid>>5] = s; sm[8 + (tid>>5)] = sq; }
  __syncthreads();
  if (tid == 0){
    float S = 0.f, SQ = 0.f;
    int nw = blockDim.x >> 5;
    for (int w = 0; w < nw; w++){ S += sm[w]; SQ += sm[8+w]; }
    atomicAdd(&g_red[which][b][0], S);
    atomicAdd(&g_red[which][b][1], SQ);
  }
}

__device__ __forceinline__ void ln_params(int which, int b, float& mean, float& rstd){
  float s  = g_red[which][b][0];
  float sq = g_red[which][b][1];
  const float M = 131072.f;
  mean = s / M;
  float var = (sq - s*s/M) / (M - 1.f);
  rstd = rsqrtf(var + 1e-5f);
}

// ---------------- K1: QKV projections (+ zero g_red from block (0,0)) ------
__global__ void __launch_bounds__(256) qkv_kernel(const float* __restrict__ x,
    const float* __restrict__ Wq, const float* __restrict__ Wk,
    const float* __restrict__ Wv){
  extern __shared__ float sm[];
  float* As = sm;             // 64*128
  float* Ws = sm + 64*128;    // 128*128
  int row0 = blockIdx.x * 64;
  const float* W = (blockIdx.y==0) ? Wq : (blockIdx.y==1 ? Wk : Wv);
  float* outp    = (blockIdx.y==0) ? g_Q : (blockIdx.y==1 ? g_K : g_V);
  int tid = threadIdx.x;

  if (blockIdx.x == 0 && blockIdx.y == 0 && tid < 32)
    ((float*)g_red)[tid] = 0.f;

  #pragma unroll
  for (int rep = 0; rep < 8; rep++){
    int idx = rep*256 + tid;
    ((float4*)As)[idx] = ((const float4*)(x + (size_t)row0*128))[idx];
  }
  #pragma unroll
  for (int rep = 0; rep < 16; rep++){
    int idx = rep*256 + tid;               // Ws[e][j], j = h*32+k
    int e = idx >> 5, j4 = idx & 31;
    ((float4*)Ws)[idx] =
      *(const float4*)(W + ((j4>>3)<<12) + (e<<5) + ((j4&7)<<2));
  }
  __syncthreads();

  int tr = tid >> 5, lane = tid & 31;
  int r0 = tr*8, c0 = lane*4;
  u64 acc[8][2];
  #pragma unroll
  for (int i=0;i<8;i++){ acc[i][0]=splat2(0.f); acc[i][1]=splat2(0.f); }
  gemm_compute2(As, Ws, acc, r0, lane);
  #pragma unroll
  for (int i=0;i<8;i++){
    float c[4];
    unpack2(acc[i][0], c[0], c[1]); unpack2(acc[i][1], c[2], c[3]);
    *(float4*)(outp + (size_t)(row0+r0+i)*128 + c0) =
      make_float4(c[0],c[1],c[2],c[3]);
  }
}

// ---------------- K2: fused attention, 512 threads, tf32 tensor cores ------
// grid (16, 8). Scores and P@V run on mma.sync.m16n8k8.tf32.
// Q/K staged to smem tf32-rounded with per-word XOR  w' = (k4&24)|((k4&7)^(m&7))
// (B/A fragment loads then hit 32 distinct banks); V staged with ^(m&3).
// Smat is plain [4*64 rows][stride 68]; P is stored tf32-rounded by softmax.
#define SM_ST 68
__global__ void __launch_bounds__(512,1) attn_kernel(
    const float* __restrict__ in2, float* __restrict__ out2,
    const float* __restrict__ Ws1, const float* __restrict__ bs1,
    const float* __restrict__ Ws2, const float* __restrict__ bs2){
  extern __shared__ float sm[];
  float* Qs      = sm;               // 64*128 tf32, xor(m&7)
  float* Ks      = Qs + 8192;        // 64*128 tf32, xor(m&7)
  float* Vs      = Ks + 8192;        // 64*128 tf32, xor(m&3)
  float* Smat    = Vs + 8192;        // 256 x SM_ST (plain columns)
  float* alpha_s = Smat + 256*SM_ST; // 256
  float* rsum_s  = alpha_s + 256;    // 256
  float* mw      = rsum_s + 256;     // 112 (8B-aligned)

  const u32* Qsu = (const u32*)Qs;
  const u32* Ksu = (const u32*)Ks;
  const u32* Vsu = (const u32*)Vs;
  const u32* Smu = (const u32*)Smat;

  int tid = threadIdx.x;
  int n0  = blockIdx.x * 64;
  int b   = blockIdx.y;

  if (tid < 64)       mw[tid] = Ws1[tid];
  else if (tid < 72)  mw[tid] = bs1[tid-64];
  else if (tid < 104) mw[tid] = Ws2[tid-72];
  else if (tid < 108) mw[tid] = bs2[tid-104];

  // MLP layer-1 weights in registers, packed over the 8 output channels
  u64 w1[8][4];
  #pragma unroll
  for (int i=0;i<8;i++)
    #pragma unroll
    for (int jp=0;jp<4;jp++)
      w1[i][jp] = *(const u64*)(Ws1 + i*8 + 2*jp);

  // stage Q tile: tf32 + xor(m&7)
  {
    const float* Qg = g_Q + ((size_t)(b*1024 + n0))*128;
    #pragma unroll
    for (int rep = 0; rep < 4; rep++){
      int idx = rep*512 + tid; int m = idx>>5, k4 = idx&31;
      float4 v = ((const float4*)Qg)[idx];
      v.x = tf32r(v.x); v.y = tf32r(v.y); v.z = tf32r(v.z); v.w = tf32r(v.w);
      int w = (k4 & 24) | ((k4 & 7) ^ (m & 7));
      *(float4*)(Qs + m*128 + w*4) = v;
    }
  }

  int wid = tid >> 5, lane = tid & 31;
  int h = wid >> 2, strip = (wid & 3)*16;   // warp: head h, q rows [strip,strip+16)
  int grp = lane >> 2, tig = lane & 3;
  int row0 = strip + grp;                   // q row (tile-local), +8 for upper
  int arow0 = (h<<6) + row0;                // Smat row
  int m_ni = tid >> 3, m_mi0 = (tid & 7)*8; // MLP mapping
  int sm_row = tid >> 1, sm_half = tid & 1; // softmax mapping

  float oAcc[4][4];
  #pragma unroll
  for (int nb=0;nb<4;nb++)
    #pragma unroll
    for (int j=0;j<4;j++) oAcc[nb][j] = 0.f;
  float rmax = -1e30f, rsum = 0.f;
  const u64 log2e2 = splat2(LOG2E);

  const float* in2b = in2  + (size_t)b*1048576;
  float*       o2b  = out2 + (size_t)b*1048576;

  for (int it = 0; it < 16; it++){
    int m0 = it*64;
    __syncthreads();
    // stage K (xor m&7) and V (xor m&3), tf32-rounded
    {
      const float* Kg = g_K + ((size_t)(b*1024 + m0))*128;
      const float* Vg = g_V + ((size_t)(b*1024 + m0))*128;
      #pragma unroll
      for (int rep = 0; rep < 4; rep++){
        int idx = rep*512 + tid; int m = idx>>5, k4 = idx&31;
        float4 kv = ((const float4*)Kg)[idx];
        kv.x=tf32r(kv.x); kv.y=tf32r(kv.y); kv.z=tf32r(kv.z); kv.w=tf32r(kv.w);
        int wk = (k4 & 24) | ((k4 & 7) ^ (m & 7));
        *(float4*)(Ks + m*128 + wk*4) = kv;
        float4 vv = ((const float4*)Vg)[idx];
        vv.x=tf32r(vv.x); vv.y=tf32r(vv.y); vv.z=tf32r(vv.z); vv.w=tf32r(vv.w);
        int wv = (k4 & 24) | ((k4 & 7) ^ (m & 3));
        *(float4*)(Vs + m*128 + wv*4) = vv;
      }
    }
    __syncthreads();

    // ---- scores: S[strip..strip+16][0..64) = Q_h K_h^T via 32 MMAs -------
    {
      u32 aQ[4][4];
      #pragma unroll
      for (int ks=0; ks<4; ks++){
        int w0 = (h<<3) + ((2*ks)   ^ grp);
        int w1w= (h<<3) + ((2*ks+1) ^ grp);
        aQ[ks][0] = Qsu[ row0   *128 + w0 *4 + tig];
        aQ[ks][1] = Qsu[(row0+8)*128 + w0 *4 + tig];
        aQ[ks][2] = Qsu[ row0   *128 + w1w*4 + tig];
        aQ[ks][3] = Qsu[(row0+8)*128 + w1w*4 + tig];
      }
      #pragma unroll
      for (int nb=0; nb<8; nb++){
        float c[4] = {0.f, 0.f, 0.f, 0.f};
        int m = nb*8 + grp;
        #pragma unroll
        for (int ks=0; ks<4; ks++){
          u32 b0 = Ksu[m*128 + ((h<<3) + ((2*ks)   ^ (m&7)))*4 + tig];
          u32 b1 = Ksu[m*128 + ((h<<3) + ((2*ks+1) ^ (m&7)))*4 + tig];
          mma_tf32(c, aQ[ks], b0, b1);
        }
        *(float2*)(Smat +  arow0   *SM_ST + nb*8 + 2*tig) = make_float2(c[0], c[1]);
        *(float2*)(Smat + (arow0+8)*SM_ST + nb*8 + 2*tig) = make_float2(c[2], c[3]);
      }
    }
    __syncthreads();

    // ---- 8->8(relu)->4 MLP, fused input2 read + passthrough write --------
    {
      const float* p0 = in2b + ((size_t)(n0+m_ni)<<10) + m0 + m_mi0;
      float*       q0 = o2b  + ((size_t)(n0+m_ni)<<10) + m0 + m_mi0;
      const u64* b1u = (const u64*)(mw + 64);
      #pragma unroll
      for (int half = 0; half < 2; half++){
        float4 ta[4];
        #pragma unroll
        for (int hh=0; hh<4; hh++){
          ta[hh] = *(const float4*)(p0 + (size_t)hh*8388608 + half*4);
          *(float4*)(q0 + (size_t)hh*8388608 + half*4) = ta[hh];
        }
        #pragma unroll
        for (int e4=0; e4<4; e4++){
          int mi = m_mi0 + half*4 + e4;
          float x[8];
          #pragma unroll
          for (int hh=0; hh<4; hh++)
            x[hh] = Smat[((hh<<6)+m_ni)*SM_ST + mi];
          #pragma unroll
          for (int hh=0; hh<4; hh++)
            x[4+hh] = ((const float*)&ta[hh])[e4];
          u64 z2[4] = { b1u[0], b1u[1], b1u[2], b1u[3] };
          #pragma unroll
          for (int i=0;i<8;i++){
            u64 sx = splat2(x[i]);
            #pragma unroll
            for (int jp=0;jp<4;jp++) z2[jp] = ffma2(sx, w1[i][jp], z2[jp]);
          }
          u64 y2[2];
          y2[0] = *(const u64*)(mw+104);
          y2[1] = *(const u64*)(mw+106);
          #pragma unroll
          for (int jp=0;jp<4;jp++){
            float zl, zh; unpack2(z2[jp], zl, zh);
            zl = fmaxf(zl, 0.f); zh = fmaxf(zh, 0.f);
            u64 sl = splat2(zl), sh = splat2(zh);
            int j0 = 2*jp, j1 = 2*jp+1;
            y2[0] = ffma2(sl, *(const u64*)(mw + 72 + j0*4),     y2[0]);
            y2[1] = ffma2(sl, *(const u64*)(mw + 72 + j0*4 + 2), y2[1]);
            y2[0] = ffma2(sh, *(const u64*)(mw + 72 + j1*4),     y2[0]);
            y2[1] = ffma2(sh, *(const u64*)(mw + 72 + j1*4 + 2), y2[1]);
          }
          y2[0] = fmul2(y2[0], log2e2);
          y2[1] = fmul2(y2[1], log2e2);
          float y[4];
          unpack2(y2[0], y[0], y[1]); unpack2(y2[1], y[2], y[3]);
          #pragma unroll
          for (int hh=0;hh<4;hh++)
            Smat[((hh<<6)+m_ni)*SM_ST + mi] = y[hh];
        }
      }
    }
    __syncthreads();

    // ---- online softmax: thread pair per row; store tf32-rounded P -------
    {
      float* Sr = Smat + sm_row*SM_ST + sm_half*32;
      float mt = -1e30f;
      #pragma unroll
      for (int q=0; q<16; q++){
        float2 v = *(const float2*)(Sr + 2*q);
        mt = fmaxf(mt, fmaxf(v.x, v.y));
      }
      float mo = __shfl_xor_sync(0xffffffffu, mt, 1);
      float mnew = fmaxf(rmax, fmaxf(mt, mo));
      float al = fexp2(rmax - mnew);
      float st = 0.f;
      #pragma unroll
      for (int q=0; q<16; q++){
        float2 v = *(const float2*)(Sr + 2*q);
        float p0 = tf32r(fexp2(v.x - mnew));
        float p1 = tf32r(fexp2(v.y - mnew));
        *(float2*)(Sr + 2*q) = make_float2(p0, p1);
        st += p0 + p1;
      }
      st += __shfl_xor_sync(0xffffffffu, st, 1);
      rsum = rsum*al + st;
      rmax = mnew;
      if (!sm_half){ alpha_s[sm_row] = al; rsum_s[sm_row] = rsum; }
    }
    __syncthreads();

    // ---- rescale + P @ V via 32 MMAs -------------------------------------
    {
      float al0 = alpha_s[arow0], al1 = alpha_s[arow0+8];
      #pragma unroll
      for (int nb=0; nb<4; nb++){
        oAcc[nb][0] *= al0; oAcc[nb][1] *= al0;
        oAcc[nb][2] *= al1; oAcc[nb][3] *= al1;
      }
      #pragma unroll
      for (int ks=0; ks<8; ks++){        // 64 m in steps of 8
        u32 aP[4];
        aP[0] = Smu[ arow0   *SM_ST + ks*8 + tig];
        aP[1] = Smu[(arow0+8)*SM_ST + ks*8 + tig];
        aP[2] = Smu[ arow0   *SM_ST + ks*8 + tig + 4];
        aP[3] = Smu[(arow0+8)*SM_ST + ks*8 + tig + 4];
        int mm = ks*8 + tig;
        #pragma unroll
        for (int nb=0; nb<4; nb++){
          int vk = nb*8 + grp;                     // within-head v column
          int wv = (h<<3) + ((vk>>2) ^ tig);
          u32 b0 = Vsu[ mm   *128 + wv*4 + (vk&3)];
          u32 b1 = Vsu[(mm+4)*128 + wv*4 + (vk&3)];
          mma_tf32(oAcc[nb], aP, b0, b1);
        }
      }
    }
  }

  // final normalize + write heads output (O[q][h*32+vk])
  {
    float inv0 = 1.f / rsum_s[arow0];
    float inv1 = 1.f / rsum_s[arow0+8];
    float* Og = g_O + ((size_t)(b*1024 + n0))*128;
    #pragma unroll
    for (int nb=0; nb<4; nb++){
      int col = (h<<5) + nb*8 + 2*tig;
      *(float2*)(Og + (size_t)(row0  )*128 + col) =
        make_float2(oAcc[nb][0]*inv0, oAcc[nb][1]*inv0);
      *(float2*)(Og + (size_t)(row0+8)*128 + col) =
        make_float2(oAcc[nb][2]*inv1, oAcc[nb][3]*inv1);
    }
  }
}

// ---------------- K3: out-projection + residual + LN0 sums -----------------
__global__ void __launch_bounds__(256) outproj_kernel(
    const float* __restrict__ input1, const float* __restrict__ Wout){
  extern __shared__ float sm[];
  float* As = sm; float* Ws = sm + 64*128;
  int row0 = blockIdx.x * 64; int tid = threadIdx.x;
  #pragma unroll
  for (int rep=0; rep<8; rep++){
    int idx = rep*256 + tid;
    ((float4*)As)[idx] = ((const float4*)(g_O + (size_t)row0*128))[idx];
  }
  #pragma unroll
  for (int rep=0; rep<16; rep++){
    int idx = rep*256 + tid;
    ((float4*)Ws)[idx] = ((const float4*)Wout)[idx];
  }
  __syncthreads();
  int tr = tid>>5, lane = tid&31, r0 = tr*8, c0 = lane*4;
  u64 acc[8][2];
  #pragma unroll
  for (int i=0;i<8;i++){ acc[i][0]=splat2(0.f); acc[i][1]=splat2(0.f); }
  gemm_compute2(As, Ws, acc, r0, lane);
  float s=0.f, sq=0.f;
  #pragma unroll
  for (int i=0;i<8;i++){
    float c[4];
    unpack2(acc[i][0], c[0], c[1]); unpack2(acc[i][1], c[2], c[3]);
    float4 res = *(const float4*)(input1 + (size_t)(row0+r0+i)*128 + c0);
    float4 o = make_float4(c[0]+res.x, c[1]+res.y, c[2]+res.z, c[3]+res.w);
    *(float4*)(g_Y + (size_t)(row0+r0+i)*128 + c0) = o;
    s  += o.x+o.y+o.z+o.w;
    sq += o.x*o.x+o.y*o.y+o.z*o.z+o.w*o.w;
  }
  ln_reduce_store(s, sq, sm, tid, row0>>10, 0);
}

// ---------------- K4: FF1 (inline LN0 of g_Y, relu) ------------------------
__global__ void __launch_bounds__(256) ff1_kernel(const float* __restrict__ Wff1){
  extern __shared__ float sm[];
  float* As = sm; float* Ws = sm + 64*128;
  int row0 = blockIdx.x * 64, ct = blockIdx.y, tid = threadIdx.x;
  float mean, rstd; ln_params(0, row0>>10, mean, rstd);
  #pragma unroll
  for (int rep=0; rep<8; rep++){
    int idx = rep*256 + tid;
    float4 v = ((const float4*)(g_Y + (size_t)row0*128))[idx];
    v.x=(v.x-mean)*rstd; v.y=(v.y-mean)*rstd;
    v.z=(v.z-mean)*rstd; v.w=(v.w-mean)*rstd;
    ((float4*)As)[idx] = v;
  }
  #pragma unroll
  for (int rep=0; rep<16; rep++){
    int idx = rep*256 + tid;
    int e = idx>>5, c4 = idx&31;
    ((float4*)Ws)[idx] = *(const float4*)(Wff1 + (size_t)e*512 + ct*128 + c4*4);
  }
  __syncthreads();
  int tr = tid>>5, lane = tid&31, r0 = tr*8, c0 = lane*4;
  u64 acc[8][2];
  #pragma unroll
  for (int i=0;i<8;i++){ acc[i][0]=splat2(0.f); acc[i][1]=splat2(0.f); }
  gemm_compute2(As, Ws, acc, r0, lane);
  #pragma unroll
  for (int i=0;i<8;i++){
    float c[4];
    unpack2(acc[i][0], c[0], c[1]); unpack2(acc[i][1], c[2], c[3]);
    float4 o = make_float4(fmaxf(c[0],0.f), fmaxf(c[1],0.f),
                           fmaxf(c[2],0.f), fmaxf(c[3],0.f));
    *(float4*)(g_FF + (size_t)(row0+r0+i)*512 + ct*128 + c0) = o;
  }
}

// ---------------- K5: FF2 + residual (inline LN0) + LN1 sums ---------------
__global__ void __launch_bounds__(256) ff2_kernel(const float* __restrict__ Wff2){
  extern __shared__ float sm[];
  float* As = sm; float* Ws = sm + 64*128;
  int row0 = blockIdx.x * 64, tid = threadIdx.x;
  float mean, rstd; ln_params(0, row0>>10, mean, rstd);
  int tr = tid>>5, lane = tid&31, r0 = tr*8, c0 = lane*4;
  u64 acc[8][2];
  #pragma unroll
  for (int i=0;i<8;i++){ acc[i][0]=splat2(0.f); acc[i][1]=splat2(0.f); }
  for (int ch = 0; ch < 4; ch++){
    __syncthreads();
    #pragma unroll
    for (int rep=0; rep<8; rep++){
      int idx = rep*256 + tid; int r = idx>>5, k4 = idx&31;
      ((float4*)As)[idx] =
        *(const float4*)(g_FF + (size_t)(row0+r)*512 + ch*128 + k4*4);
    }
    #pragma unroll
    for (int rep=0; rep<16; rep++){
      int idx = rep*256 + tid;
      ((float4*)Ws)[idx] = ((const float4*)(Wff2 + (size_t)ch*16384))[idx];
    }
    __syncthreads();
    gemm_compute2(As, Ws, acc, r0, lane);
  }
  float s=0.f, sq=0.f;
  #pragma unroll
  for (int i=0;i<8;i++){
    float c[4];
    unpack2(acc[i][0], c[0], c[1]); unpack2(acc[i][1], c[2], c[3]);
    float4 res = *(const float4*)(g_Y + (size_t)(row0+r0+i)*128 + c0);
    res.x=(res.x-mean)*rstd; res.y=(res.y-mean)*rstd;
    res.z=(res.z-mean)*rstd; res.w=(res.w-mean)*rstd;
    float4 o = make_float4(c[0]+res.x, c[1]+res.y, c[2]+res.z, c[3]+res.w);
    *(float4*)(g_Y + (size_t)(row0+r0+i)*128 + c0) = o;   // own rows only
    s  += o.x+o.y+o.z+o.w;
    sq += o.x*o.x+o.y*o.y+o.z*o.z+o.w*o.w;
  }
  ln_reduce_store(s, sq, sm, tid, row0>>10, 1);
}

// ---------------- K6: final global LayerNorm (ddof=1) ----------------------
__global__ void __launch_bounds__(256) norm_kernel(float* __restrict__ extout){
  int id = blockIdx.x*256 + threadIdx.x;          // float4 index
  int b = (id*4) >> 17;
  float mean, rstd; ln_params(1, b, mean, rstd);
  float4 v = ((const float4*)g_Y)[id];
  v.x = (v.x-mean)*rstd; v.y = (v.y-mean)*rstd;
  v.z = (v.z-mean)*rstd; v.w = (v.w-mean)*rstd;
  ((float4*)extout)[id] = v;
}

// ---------------- launcher --------------------------------------------------
extern "C" void kernel_launch(void* const* d_in, const int* in_sizes, int n_in,
                              void* d_out, int out_size){
  const float* input1 = (const float*)d_in[0];
  const float* input2 = (const float*)d_in[1];
  const float* Wq  = (const float*)d_in[2];
  const float* Wk  = (const float*)d_in[3];
  const float* Wv  = (const float*)d_in[4];
  const float* Wo  = (const float*)d_in[5];
  const float* Ws1 = (const float*)d_in[6];
  const float* bs1 = (const float*)d_in[7];
  const float* Ws2 = (const float*)d_in[8];
  const float* bs2 = (const float*)d_in[9];
  const float* Wff1 = (const float*)d_in[10];
  const float* Wff2 = (const float*)d_in[11];
  float* out1 = (float*)d_out;
  float* out2 = out1 + 8*1024*128;      // input2 passthrough region

  const int GEMM_SMEM = (64*128 + 128*128)*4;                        // 98304
  const int ATTN_SMEM = (3*8192 + 256*SM_ST + 256 + 256 + 112)*4;    // 170432

  cudaFuncSetAttribute(qkv_kernel,     cudaFuncAttributeMaxDynamicSharedMemorySize, GEMM_SMEM);
  cudaFuncSetAttribute(attn_kernel,    cudaFuncAttributeMaxDynamicSharedMemorySize, ATTN_SMEM);
  cudaFuncSetAttribute(outproj_kernel, cudaFuncAttributeMaxDynamicSharedMemorySize, GEMM_SMEM);
  cudaFuncSetAttribute(ff1_kernel,     cudaFuncAttributeMaxDynamicSharedMemorySize, GEMM_SMEM);
  cudaFuncSetAttribute(ff2_kernel,     cudaFuncAttributeMaxDynamicSharedMemorySize, GEMM_SMEM);

  qkv_kernel<<<dim3(128,3), 256, GEMM_SMEM>>>(input1, Wq, Wk, Wv);
  attn_kernel<<<dim3(16,8), 512, ATTN_SMEM>>>(input2, out2, Ws1, bs1, Ws2, bs2);
  outproj_kernel<<<128, 256, GEMM_SMEM>>>(input1, Wo);
  ff1_kernel<<<dim3(128,4), 256, GEMM_SMEM>>>(Wff1);
  ff2_kernel<<<128, 256, GEMM_SMEM>>>(Wff2);
  norm_kernel<<<1024, 256>>>(out1);
}